// round 5
// baseline (speedup 1.0000x reference)
#include <cuda_runtime.h>
#include <cstdint>

#define PPIX 3136
#define CH 256
#define DIM 32
#define KER 7
#define K2 49
#define TILE 14
#define HALO 20
#define HALOSZ 400
#define ROWP 36

// scratch (allocation-free rule: device globals)
__device__ __align__(16) float g_Qp[2 * PPIX * CH];
__device__ __align__(16) float g_Kp[2 * PPIX * CH];
__device__ __align__(16) float g_Vp[2 * PPIX * CH];
__device__ __align__(16) float g_O [2 * PPIX * CH];
__device__ __align__(16) float g_bck[CH];
__device__ __align__(16) float g_bcv[CH];

// ---------------------------------------------------------------------------
// helpers
// ---------------------------------------------------------------------------
__device__ __forceinline__ uint32_t f2tf(float x) {
    uint32_t r;
    asm("cvt.rna.tf32.f32 %0, %1;" : "=r"(r) : "f"(x));
    return r;
}
__device__ __forceinline__ uint4 cvt4(float4 v) {
    uint4 u;
    u.x = f2tf(v.x); u.y = f2tf(v.y); u.z = f2tf(v.z); u.w = f2tf(v.w);
    return u;
}
__device__ __forceinline__ void mma_tf32(float c[4], const uint32_t a[4], const uint32_t b[2]) {
    asm volatile(
        "mma.sync.aligned.m16n8k8.row.col.f32.tf32.tf32.f32 "
        "{%0,%1,%2,%3}, {%4,%5,%6,%7}, {%8,%9}, {%0,%1,%2,%3};"
        : "+f"(c[0]), "+f"(c[1]), "+f"(c[2]), "+f"(c[3])
        : "r"(a[0]), "r"(a[1]), "r"(a[2]), "r"(a[3]), "r"(b[0]), "r"(b[1]));
}

// ---------------------------------------------------------------------------
// bconst[c'] = pos * sum_c W[c'][c] + b[c']   (K and V blocks of in_proj)
// ---------------------------------------------------------------------------
__global__ void bconst_kernel(const float* __restrict__ W, const float* __restrict__ b,
                              const float* __restrict__ pos) {
    int c = blockIdx.x * 8 + (threadIdx.x >> 5);
    int lane = threadIdx.x & 31;
    float p = pos[0];
    const float4* wk = reinterpret_cast<const float4*>(W + (size_t)(CH + c) * CH);
    const float4* wv = reinterpret_cast<const float4*>(W + (size_t)(2 * CH + c) * CH);
    float4 a0 = wk[lane * 2], a1 = wk[lane * 2 + 1];
    float4 v0 = wv[lane * 2], v1 = wv[lane * 2 + 1];
    float sk = a0.x + a0.y + a0.z + a0.w + a1.x + a1.y + a1.z + a1.w;
    float sv = v0.x + v0.y + v0.z + v0.w + v1.x + v1.y + v1.z + v1.w;
    #pragma unroll
    for (int o = 16; o > 0; o >>= 1) {
        sk += __shfl_xor_sync(0xffffffffu, sk, o);
        sv += __shfl_xor_sync(0xffffffffu, sv, o);
    }
    if (lane == 0) {
        g_bck[c] = p * sk + b[CH + c];
        g_bcv[c] = p * sv + b[2 * CH + c];
    }
}

// ---------------------------------------------------------------------------
// Projection GEMM (tf32, BM=64 BN=64 BK=32, double-buffered, 128 threads,
// 4 CTAs/SM): Out[p][c'] = sum_c W[c'][c] * In[c][p]  (+ bias for Q only)
// 4 warps 2m x 2n, warp tile 32x32.
// In channel-major (C,P) -> A smem k-major [32][72].
// W row-major (n,k)      -> B smem n-major [64][36].
// blockIdx.z = proj*2 + n
// ---------------------------------------------------------------------------
__global__ void __launch_bounds__(128, 4)
proj_gemm(const float* __restrict__ queries, const float* __restrict__ key,
          const float* __restrict__ Wall, const float* __restrict__ bvec) {
    int proj = blockIdx.z >> 1;
    int n    = blockIdx.z & 1;
    const float* In = ((proj == 0) ? queries : key) + (size_t)n * CH * PPIX;
    const float* W  = Wall + (size_t)proj * CH * CH;
    float* Out = (proj == 0 ? g_Qp : (proj == 1 ? g_Kp : g_Vp)) + (size_t)n * PPIX * CH;

    extern __shared__ uint32_t sm[];
    uint32_t* As = sm;                 // [2][32][72]
    uint32_t* Bs = sm + 2 * 2304;      // [2][64][36]

    int tid = threadIdx.x;
    int m0 = blockIdx.x * 64;
    int c0 = blockIdx.y * 64;
    int w = tid >> 5, lane = tid & 31;
    int r = lane >> 2, tig = lane & 3;
    int wm = (w & 1) * 32;
    int wn = (w >> 1) * 32;

    int a_k  = tid >> 4;            // 0..7 (+8*i)
    int a_m4 = (tid & 15) * 4;
    int b_n  = tid >> 3;            // 0..15 (+16*i)
    int b_k4 = (tid & 7) * 4;

    float acc[2][4][4] = {};
    float4 sa[4], sb[4];

    auto load_tile = [&](int kt) {
        #pragma unroll
        for (int i = 0; i < 4; i++)
            sa[i] = *reinterpret_cast<const float4*>(In + (size_t)(kt + a_k + 8 * i) * PPIX + m0 + a_m4);
        #pragma unroll
        for (int i = 0; i < 4; i++)
            sb[i] = *reinterpret_cast<const float4*>(W + (size_t)(c0 + b_n + 16 * i) * CH + kt + b_k4);
    };
    auto store_tile = [&](int buf) {
        uint32_t* Ab = As + buf * 2304;
        uint32_t* Bb = Bs + buf * 2304;
        #pragma unroll
        for (int i = 0; i < 4; i++)
            *reinterpret_cast<uint4*>(Ab + (a_k + 8 * i) * 72 + a_m4) = cvt4(sa[i]);
        #pragma unroll
        for (int i = 0; i < 4; i++)
            *reinterpret_cast<uint4*>(Bb + (b_n + 16 * i) * 36 + b_k4) = cvt4(sb[i]);
    };

    load_tile(0);
    store_tile(0);
    __syncthreads();

    int buf = 0;
    for (int it = 0; it < 8; it++) {
        if (it < 7) load_tile((it + 1) * 32);
        const uint32_t* Ab = As + buf * 2304;
        const uint32_t* Bb = Bs + buf * 2304;
        #pragma unroll
        for (int ks = 0; ks < 4; ks++) {
            int k0 = ks * 8;
            uint32_t a[2][4], b[4][2];
            #pragma unroll
            for (int mt = 0; mt < 2; mt++) {
                int m = wm + mt * 16 + r;
                a[mt][0] = Ab[(k0 + tig) * 72 + m];
                a[mt][1] = Ab[(k0 + tig) * 72 + m + 8];
                a[mt][2] = Ab[(k0 + tig + 4) * 72 + m];
                a[mt][3] = Ab[(k0 + tig + 4) * 72 + m + 8];
            }
            #pragma unroll
            for (int nt = 0; nt < 4; nt++) {
                int nn = wn + nt * 8 + r;
                b[nt][0] = Bb[nn * 36 + k0 + tig];
                b[nt][1] = Bb[nn * 36 + k0 + tig + 4];
            }
            #pragma unroll
            for (int mt = 0; mt < 2; mt++)
                #pragma unroll
                for (int nt = 0; nt < 4; nt++)
                    mma_tf32(acc[mt][nt], a[mt], b[nt]);
        }
        if (it < 7) {
            store_tile(buf ^ 1);
            __syncthreads();
            buf ^= 1;
        }
    }

    #pragma unroll
    for (int mt = 0; mt < 2; mt++) {
        int row0 = m0 + wm + mt * 16 + r;
        #pragma unroll
        for (int nt = 0; nt < 4; nt++) {
            int cc = c0 + wn + nt * 8 + 2 * tig;
            float b0 = (proj == 0) ? bvec[cc] : 0.f;
            float b1 = (proj == 0) ? bvec[cc + 1] : 0.f;
            *reinterpret_cast<float2*>(Out + (size_t)row0 * CH + cc) =
                make_float2(acc[mt][nt][0] + b0, acc[mt][nt][1] + b1);
            *reinterpret_cast<float2*>(Out + (size_t)(row0 + 8) * CH + cc) =
                make_float2(acc[mt][nt][2] + b0, acc[mt][nt][3] + b1);
        }
    }
}

// ---------------------------------------------------------------------------
// Local attention, 2 pixels (horizontal pair) per thread: shared 7x8 K/V
// window cuts LDS traffic 1.75x.  Phase-split smem (K then V, same buffer).
// One block = 14x14 pixels, one (n, head); 98 compute threads of 128.
// ---------------------------------------------------------------------------
__global__ void __launch_bounds__(128, 2) attn_kernel() {
    extern __shared__ float smf[];     // HALOSZ * ROWP floats

    int tx0 = blockIdx.x * TILE;
    int ty0 = blockIdx.y * TILE;
    int h = blockIdx.z & 7;
    int n = blockIdx.z >> 3;
    int tid = threadIdx.x;
    int cbase = h * DIM;

    const float* Kp = g_Kp + (size_t)n * PPIX * CH;
    const float* Vp = g_Vp + (size_t)n * PPIX * CH;

    int py  = tid / 7;
    int px2 = (tid % 7) * 2;
    bool active = tid < 98;
    int pL = (ty0 + py) * 56 + (tx0 + px2);

    float4 qL[8], qR[8];
    if (active) {
        const float* qp = g_Qp + (size_t)n * PPIX * CH + (size_t)pL * CH + cbase;
        #pragma unroll
        for (int i = 0; i < 8; i++) {
            qL[i] = *reinterpret_cast<const float4*>(qp + i * 4);
            qR[i] = *reinterpret_cast<const float4*>(qp + CH + i * 4);
        }
    }

    // ---- phase 1: K halo fill ----
    for (int idx = tid; idx < HALOSZ * 8; idx += 128) {
        int hp = idx >> 3;
        int c4 = (idx & 7) * 4;
        int gy = ty0 - 3 + hp / HALO;
        int gx = tx0 - 3 + hp % HALO;
        float4 kv = *reinterpret_cast<const float4*>(g_bck + cbase + c4);
        if (gy >= 0 && gy < 56 && gx >= 0 && gx < 56) {
            float4 k4 = *reinterpret_cast<const float4*>(Kp + (size_t)(gy * 56 + gx) * CH + cbase + c4);
            kv.x += k4.x; kv.y += k4.y; kv.z += k4.z; kv.w += k4.w;
        }
        *reinterpret_cast<float4*>(smf + hp * ROWP + c4) = kv;
    }
    __syncthreads();

    float scL[K2], scR[K2];
    if (active) {
        const float scale = 0.17677669529663687f;   // 1/sqrt(32)
        #pragma unroll
        for (int ti = 0; ti < KER; ti++) {
            #pragma unroll
            for (int tj = 0; tj < 8; tj++) {
                const float4* kr = reinterpret_cast<const float4*>(
                    smf + ((py + ti) * HALO + (px2 + tj)) * ROWP);
                float4 k[8];
                #pragma unroll
                for (int c = 0; c < 8; c++) k[c] = kr[c];
                if (tj < 7) {
                    float s = 0.f;
                    #pragma unroll
                    for (int c = 0; c < 8; c++)
                        s += qL[c].x * k[c].x + qL[c].y * k[c].y + qL[c].z * k[c].z + qL[c].w * k[c].w;
                    scL[ti * KER + tj] = s * scale;
                }
                if (tj >= 1) {
                    float s = 0.f;
                    #pragma unroll
                    for (int c = 0; c < 8; c++)
                        s += qR[c].x * k[c].x + qR[c].y * k[c].y + qR[c].z * k[c].z + qR[c].w * k[c].w;
                    scR[ti * KER + tj - 1] = s * scale;
                }
            }
        }
        float mxL = scL[0], mxR = scR[0];
        #pragma unroll
        for (int t = 1; t < K2; t++) { mxL = fmaxf(mxL, scL[t]); mxR = fmaxf(mxR, scR[t]); }
        float suL = 0.f, suR = 0.f;
        #pragma unroll
        for (int t = 0; t < K2; t++) {
            scL[t] = __expf(scL[t] - mxL); suL += scL[t];
            scR[t] = __expf(scR[t] - mxR); suR += scR[t];
        }
        float ivL = 1.f / suL, ivR = 1.f / suR;
        #pragma unroll
        for (int t = 0; t < K2; t++) { scL[t] *= ivL; scR[t] *= ivR; }
    }
    __syncthreads();

    // ---- phase 2: V halo fill (same buffer) ----
    for (int idx = tid; idx < HALOSZ * 8; idx += 128) {
        int hp = idx >> 3;
        int c4 = (idx & 7) * 4;
        int gy = ty0 - 3 + hp / HALO;
        int gx = tx0 - 3 + hp % HALO;
        float4 vv = *reinterpret_cast<const float4*>(g_bcv + cbase + c4);
        if (gy >= 0 && gy < 56 && gx >= 0 && gx < 56) {
            float4 v4 = *reinterpret_cast<const float4*>(Vp + (size_t)(gy * 56 + gx) * CH + cbase + c4);
            vv.x += v4.x; vv.y += v4.y; vv.z += v4.z; vv.w += v4.w;
        }
        *reinterpret_cast<float4*>(smf + hp * ROWP + c4) = vv;
    }
    __syncthreads();

    if (active) {
        float4 oL[8], oR[8];
        #pragma unroll
        for (int c = 0; c < 8; c++) {
            oL[c] = make_float4(0.f, 0.f, 0.f, 0.f);
            oR[c] = make_float4(0.f, 0.f, 0.f, 0.f);
        }
        #pragma unroll
        for (int ti = 0; ti < KER; ti++) {
            #pragma unroll
            for (int tj = 0; tj < 8; tj++) {
                const float4* vr = reinterpret_cast<const float4*>(
                    smf + ((py + ti) * HALO + (px2 + tj)) * ROWP);
                float4 v[8];
                #pragma unroll
                for (int c = 0; c < 8; c++) v[c] = vr[c];
                if (tj < 7) {
                    float wg = scL[ti * KER + tj];
                    #pragma unroll
                    for (int c = 0; c < 8; c++) {
                        oL[c].x += wg * v[c].x; oL[c].y += wg * v[c].y;
                        oL[c].z += wg * v[c].z; oL[c].w += wg * v[c].w;
                    }
                }
                if (tj >= 1) {
                    float wg = scR[ti * KER + tj - 1];
                    #pragma unroll
                    for (int c = 0; c < 8; c++) {
                        oR[c].x += wg * v[c].x; oR[c].y += wg * v[c].y;
                        oR[c].z += wg * v[c].z; oR[c].w += wg * v[c].w;
                    }
                }
            }
        }
        float* op = g_O + (size_t)n * PPIX * CH + (size_t)pL * CH + cbase;
        #pragma unroll
        for (int i = 0; i < 8; i++) {
            *reinterpret_cast<float4*>(op + i * 4)      = oL[i];
            *reinterpret_cast<float4*>(op + CH + i * 4) = oR[i];
        }
    }
}

// ---------------------------------------------------------------------------
// Out projection (tf32, BM=64 BN=64 BK=32, double-buffered, 128 threads,
// 4 CTAs/SM): out[n][c'][p] = sum_c O[n][p][c] * Wout[c'][c] + bout[c']
// O row-major (m,k) -> A smem m-major [64][36].
// ---------------------------------------------------------------------------
__global__ void __launch_bounds__(128, 4)
outproj_gemm(const float* __restrict__ Wout, const float* __restrict__ bout,
             float* __restrict__ out) {
    int nb = blockIdx.z;
    const float* A = g_O + (size_t)nb * PPIX * CH;

    extern __shared__ uint32_t sm[];
    uint32_t* As = sm;                 // [2][64][36]
    uint32_t* Bs = sm + 2 * 2304;      // [2][64][36]

    int tid = threadIdx.x;
    int m0 = blockIdx.x * 64;
    int c0 = blockIdx.y * 64;
    int w = tid >> 5, lane = tid & 31;
    int r = lane >> 2, tig = lane & 3;
    int wm = (w & 1) * 32;
    int wn = (w >> 1) * 32;

    int a_m  = tid >> 3;            // 0..15 (+16*i)
    int a_k4 = (tid & 7) * 4;
    int b_n  = tid >> 3;
    int b_k4 = (tid & 7) * 4;

    float acc[2][4][4] = {};
    float4 sa[4], sb[4];

    auto load_tile = [&](int kt) {
        #pragma unroll
        for (int i = 0; i < 4; i++)
            sa[i] = *reinterpret_cast<const float4*>(A + (size_t)(m0 + a_m + 16 * i) * CH + kt + a_k4);
        #pragma unroll
        for (int i = 0; i < 4; i++)
            sb[i] = *reinterpret_cast<const float4*>(Wout + (size_t)(c0 + b_n + 16 * i) * CH + kt + b_k4);
    };
    auto store_tile = [&](int buf) {
        uint32_t* Ab = As + buf * 2304;
        uint32_t* Bb = Bs + buf * 2304;
        #pragma unroll
        for (int i = 0; i < 4; i++)
            *reinterpret_cast<uint4*>(Ab + (a_m + 16 * i) * 36 + a_k4) = cvt4(sa[i]);
        #pragma unroll
        for (int i = 0; i < 4; i++)
            *reinterpret_cast<uint4*>(Bb + (b_n + 16 * i) * 36 + b_k4) = cvt4(sb[i]);
    };

    load_tile(0);
    store_tile(0);
    __syncthreads();

    int buf = 0;
    for (int it = 0; it < 8; it++) {
        if (it < 7) load_tile((it + 1) * 32);
        const uint32_t* Ab = As + buf * 2304;
        const uint32_t* Bb = Bs + buf * 2304;
        #pragma unroll
        for (int ks = 0; ks < 4; ks++) {
            int k0 = ks * 8;
            uint32_t a[2][4], b[4][2];
            #pragma unroll
            for (int mt = 0; mt < 2; mt++) {
                int m = wm + mt * 16 + r;
                a[mt][0] = Ab[m * 36 + k0 + tig];
                a[mt][1] = Ab[(m + 8) * 36 + k0 + tig];
                a[mt][2] = Ab[m * 36 + k0 + tig + 4];
                a[mt][3] = Ab[(m + 8) * 36 + k0 + tig + 4];
            }
            #pragma unroll
            for (int nt = 0; nt < 4; nt++) {
                int nn = wn + nt * 8 + r;
                b[nt][0] = Bb[nn * 36 + k0 + tig];
                b[nt][1] = Bb[nn * 36 + k0 + tig + 4];
            }
            #pragma unroll
            for (int mt = 0; mt < 2; mt++)
                #pragma unroll
                for (int nt = 0; nt < 4; nt++)
                    mma_tf32(acc[mt][nt], a[mt], b[nt]);
        }
        if (it < 7) {
            store_tile(buf ^ 1);
            __syncthreads();
            buf ^= 1;
        }
    }

    // epilogue: transposed store out[c'][p]
    float* ob = out + (size_t)nb * CH * PPIX;
    #pragma unroll
    for (int mt = 0; mt < 2; mt++) {
        int row0 = m0 + wm + mt * 16 + r;
        #pragma unroll
        for (int nt = 0; nt < 4; nt++) {
            int cc = c0 + wn + nt * 8 + 2 * tig;
            float b0 = bout[cc], b1 = bout[cc + 1];
            ob[(size_t)cc * PPIX + row0]           = acc[mt][nt][0] + b0;
            ob[(size_t)(cc + 1) * PPIX + row0]     = acc[mt][nt][1] + b1;
            ob[(size_t)cc * PPIX + row0 + 8]       = acc[mt][nt][2] + b0;
            ob[(size_t)(cc + 1) * PPIX + row0 + 8] = acc[mt][nt][3] + b1;
        }
    }
}

extern "C" void kernel_launch(void* const* d_in, const int* in_sizes, int n_in,
                              void* d_out, int out_size) {
    const float* queries = (const float*)d_in[0];
    const float* key     = (const float*)d_in[1];
    const float* pos     = (const float*)d_in[2];
    const float* ipw     = (const float*)d_in[3];
    const float* ipb     = (const float*)d_in[4];
    const float* opw     = (const float*)d_in[5];
    const float* opb     = (const float*)d_in[6];
    float* out = (float*)d_out;

    const int gemm_smem = (2 * 2304 + 2 * 2304) * (int)sizeof(uint32_t);   // 36864
    const int attn_smem = HALOSZ * ROWP * (int)sizeof(float);              // 57600

    cudaFuncSetAttribute(proj_gemm,    cudaFuncAttributeMaxDynamicSharedMemorySize, gemm_smem);
    cudaFuncSetAttribute(outproj_gemm, cudaFuncAttributeMaxDynamicSharedMemorySize, gemm_smem);
    cudaFuncSetAttribute(attn_kernel,  cudaFuncAttributeMaxDynamicSharedMemorySize, attn_smem);

    bconst_kernel<<<32, 256>>>(ipw, ipb, pos);
    proj_gemm<<<dim3(49, 4, 6), 128, gemm_smem>>>(queries, key, ipw, ipb);
    attn_kernel<<<dim3(4, 4, 16), 128, attn_smem>>>();
    outproj_gemm<<<dim3(49, 4, 2), 128, gemm_smem>>>(opw, opb, out);
}

// round 6
// speedup vs baseline: 1.0719x; 1.0719x over previous
#include <cuda_runtime.h>
#include <cstdint>

#define PPIX 3136
#define CH 256
#define DIM 32
#define KER 7
#define K2 49
#define TILE 14
#define HALO 20
#define HALOSZ 400
#define ROWP 36

// scratch (allocation-free rule: device globals)
__device__ __align__(16) float g_Qp[2 * PPIX * CH];
__device__ __align__(16) float g_Kp[2 * PPIX * CH];
__device__ __align__(16) float g_Vp[2 * PPIX * CH];
__device__ __align__(16) float g_O [2 * PPIX * CH];
__device__ __align__(16) float g_bck[CH];
__device__ __align__(16) float g_bcv[CH];

// ---------------------------------------------------------------------------
// helpers
// ---------------------------------------------------------------------------
__device__ __forceinline__ uint32_t f2tf(float x) {
    uint32_t r;
    asm("cvt.rna.tf32.f32 %0, %1;" : "=r"(r) : "f"(x));
    return r;
}
__device__ __forceinline__ void mma_tf32(float c[4], const uint32_t a[4], const uint32_t b[2]) {
    asm volatile(
        "mma.sync.aligned.m16n8k8.row.col.f32.tf32.tf32.f32 "
        "{%0,%1,%2,%3}, {%4,%5,%6,%7}, {%8,%9}, {%0,%1,%2,%3};"
        : "+f"(c[0]), "+f"(c[1]), "+f"(c[2]), "+f"(c[3])
        : "r"(a[0]), "r"(a[1]), "r"(a[2]), "r"(a[3]), "r"(b[0]), "r"(b[1]));
}
__device__ __forceinline__ void cp16(float* smem_dst, const float* gmem_src) {
    uint32_t s = (uint32_t)__cvta_generic_to_shared(smem_dst);
    asm volatile("cp.async.cg.shared.global [%0], [%1], 16;" :: "r"(s), "l"(gmem_src));
}
#define CP_COMMIT()  asm volatile("cp.async.commit_group;")
#define CP_WAIT1()   asm volatile("cp.async.wait_group 1;")

// GEMM smem geometry (floats): per stage A tile 2304 + B tile 2304
#define STG_F 4608
#define NSTG 3

// ---------------------------------------------------------------------------
// bconst[c'] = pos * sum_c W[c'][c] + b[c']   (K and V blocks of in_proj)
// ---------------------------------------------------------------------------
__global__ void bconst_kernel(const float* __restrict__ W, const float* __restrict__ b,
                              const float* __restrict__ pos) {
    int c = blockIdx.x * 8 + (threadIdx.x >> 5);
    int lane = threadIdx.x & 31;
    float p = pos[0];
    const float4* wk = reinterpret_cast<const float4*>(W + (size_t)(CH + c) * CH);
    const float4* wv = reinterpret_cast<const float4*>(W + (size_t)(2 * CH + c) * CH);
    float4 a0 = wk[lane * 2], a1 = wk[lane * 2 + 1];
    float4 v0 = wv[lane * 2], v1 = wv[lane * 2 + 1];
    float sk = a0.x + a0.y + a0.z + a0.w + a1.x + a1.y + a1.z + a1.w;
    float sv = v0.x + v0.y + v0.z + v0.w + v1.x + v1.y + v1.z + v1.w;
    #pragma unroll
    for (int o = 16; o > 0; o >>= 1) {
        sk += __shfl_xor_sync(0xffffffffu, sk, o);
        sv += __shfl_xor_sync(0xffffffffu, sv, o);
    }
    if (lane == 0) {
        g_bck[c] = p * sk + b[CH + c];
        g_bcv[c] = p * sv + b[2 * CH + c];
    }
}

// ---------------------------------------------------------------------------
// Projection GEMM (tf32, BM=64 BN=64 BK=32, cp.async 3-stage, 128 threads):
//   Out[p][c'] = sum_c W[c'][c] * In[c][p]  (+ bias for Q only)
// In channel-major (C,P) -> A smem k-major f32 [32][72].
// W row-major (n,k)      -> B smem n-major f32 [64][36].
// tf32 conversion happens on fragments AFTER LDS (numerically identical).
// blockIdx.z = proj*2 + n
// ---------------------------------------------------------------------------
__global__ void __launch_bounds__(128, 4)
proj_gemm(const float* __restrict__ queries, const float* __restrict__ key,
          const float* __restrict__ Wall, const float* __restrict__ bvec) {
    int proj = blockIdx.z >> 1;
    int n    = blockIdx.z & 1;
    const float* In = ((proj == 0) ? queries : key) + (size_t)n * CH * PPIX;
    const float* W  = Wall + (size_t)proj * CH * CH;
    float* Out = (proj == 0 ? g_Qp : (proj == 1 ? g_Kp : g_Vp)) + (size_t)n * PPIX * CH;

    extern __shared__ float smf[];     // [NSTG][STG_F]

    int tid = threadIdx.x;
    int m0 = blockIdx.x * 64;
    int c0 = blockIdx.y * 64;
    int w = tid >> 5, lane = tid & 31;
    int r = lane >> 2, tig = lane & 3;
    int wm = (w & 1) * 32;
    int wn = (w >> 1) * 32;

    // A chunks: 32 rows x 16 chunks;  B chunks: 64 rows x 8 chunks
    int a_row = tid >> 2;              // pattern: id = tid + 128*i
    int a_c4  = (tid & 3) * 4;         // recomputed per i below
    (void)a_row; (void)a_c4;

    float acc[2][4][4] = {};

    auto issue_tile = [&](int t, int stg) {
        float* As = smf + stg * STG_F;
        float* Bs = As + 2304;
        int kt = t * 32;
        #pragma unroll
        for (int i = 0; i < 4; i++) {
            int id = tid + 128 * i;
            int row = id >> 4;                 // 0..31
            int c4 = (id & 15) * 4;            // 0..60
            cp16(As + row * 72 + c4, In + (size_t)(kt + row) * PPIX + m0 + c4);
        }
        #pragma unroll
        for (int i = 0; i < 4; i++) {
            int id = tid + 128 * i;
            int row = id >> 3;                 // 0..63
            int k4 = (id & 7) * 4;             // 0..28
            cp16(Bs + row * 36 + k4, W + (size_t)(c0 + row) * CH + kt + k4);
        }
        CP_COMMIT();
    };

    issue_tile(0, 0);
    issue_tile(1, 1);

    for (int it = 0; it < 8; it++) {
        CP_WAIT1();
        __syncthreads();
        if (it + 2 < 8) issue_tile(it + 2, (it + 2) % NSTG);

        const float* Ab = smf + (it % NSTG) * STG_F;
        const float* Bb = Ab + 2304;
        #pragma unroll
        for (int ks = 0; ks < 4; ks++) {
            int k0 = ks * 8;
            uint32_t a[2][4], b[4][2];
            #pragma unroll
            for (int mt = 0; mt < 2; mt++) {
                int m = wm + mt * 16 + r;
                a[mt][0] = f2tf(Ab[(k0 + tig) * 72 + m]);
                a[mt][1] = f2tf(Ab[(k0 + tig) * 72 + m + 8]);
                a[mt][2] = f2tf(Ab[(k0 + tig + 4) * 72 + m]);
                a[mt][3] = f2tf(Ab[(k0 + tig + 4) * 72 + m + 8]);
            }
            #pragma unroll
            for (int nt = 0; nt < 4; nt++) {
                int nn = wn + nt * 8 + r;
                b[nt][0] = f2tf(Bb[nn * 36 + k0 + tig]);
                b[nt][1] = f2tf(Bb[nn * 36 + k0 + tig + 4]);
            }
            #pragma unroll
            for (int mt = 0; mt < 2; mt++)
                #pragma unroll
                for (int nt = 0; nt < 4; nt++)
                    mma_tf32(acc[mt][nt], a[mt], b[nt]);
        }
    }

    #pragma unroll
    for (int mt = 0; mt < 2; mt++) {
        int row0 = m0 + wm + mt * 16 + r;
        #pragma unroll
        for (int nt = 0; nt < 4; nt++) {
            int cc = c0 + wn + nt * 8 + 2 * tig;
            float b0 = (proj == 0) ? bvec[cc] : 0.f;
            float b1 = (proj == 0) ? bvec[cc + 1] : 0.f;
            *reinterpret_cast<float2*>(Out + (size_t)row0 * CH + cc) =
                make_float2(acc[mt][nt][0] + b0, acc[mt][nt][1] + b1);
            *reinterpret_cast<float2*>(Out + (size_t)(row0 + 8) * CH + cc) =
                make_float2(acc[mt][nt][2] + b0, acc[mt][nt][3] + b1);
        }
    }
}

// ---------------------------------------------------------------------------
// Local attention (round-4 proven version): 1 pixel/thread, 256 threads,
// phase-split smem (K then V in the SAME 57.6KB buffer), 2 blocks/SM.
// ---------------------------------------------------------------------------
__global__ void __launch_bounds__(256, 2) attn_kernel() {
    extern __shared__ float smf[];     // HALOSZ * ROWP floats

    int tx0 = blockIdx.x * TILE;
    int ty0 = blockIdx.y * TILE;
    int h = blockIdx.z & 7;
    int n = blockIdx.z >> 3;
    int tid = threadIdx.x;
    int cbase = h * DIM;

    const float* Kp = g_Kp + (size_t)n * PPIX * CH;
    const float* Vp = g_Vp + (size_t)n * PPIX * CH;

    int ly = tid / TILE, lx = tid % TILE;
    bool active = tid < TILE * TILE;
    int p = (ty0 + ly) * 56 + (tx0 + lx);

    float4 q4[8];
    if (active) {
        const float* qptr = g_Qp + (size_t)n * PPIX * CH + (size_t)p * CH + cbase;
        #pragma unroll
        for (int i = 0; i < 8; i++)
            q4[i] = *reinterpret_cast<const float4*>(qptr + i * 4);
    }

    // ---- phase 1: K halo fill ----
    for (int idx = tid; idx < HALOSZ * 8; idx += 256) {
        int hp = idx >> 3;
        int c4 = (idx & 7) * 4;
        int gy = ty0 - 3 + hp / HALO;
        int gx = tx0 - 3 + hp % HALO;
        float4 kv = *reinterpret_cast<const float4*>(g_bck + cbase + c4);
        if (gy >= 0 && gy < 56 && gx >= 0 && gx < 56) {
            float4 k4 = *reinterpret_cast<const float4*>(Kp + (size_t)(gy * 56 + gx) * CH + cbase + c4);
            kv.x += k4.x; kv.y += k4.y; kv.z += k4.z; kv.w += k4.w;
        }
        *reinterpret_cast<float4*>(smf + hp * ROWP + c4) = kv;
    }
    __syncthreads();

    float sc[K2];
    if (active) {
        const float scale = 0.17677669529663687f;   // 1/sqrt(32)
        #pragma unroll
        for (int ti = 0; ti < KER; ti++) {
            #pragma unroll
            for (int tj = 0; tj < KER; tj++) {
                const float4* kr = reinterpret_cast<const float4*>(
                    smf + ((ly + ti) * HALO + (lx + tj)) * ROWP);
                float s = 0.f;
                #pragma unroll
                for (int c = 0; c < 8; c++) {
                    float4 k4 = kr[c];
                    s += q4[c].x * k4.x + q4[c].y * k4.y + q4[c].z * k4.z + q4[c].w * k4.w;
                }
                sc[ti * KER + tj] = s * scale;
            }
        }
        float mx = sc[0];
        #pragma unroll
        for (int t = 1; t < K2; t++) mx = fmaxf(mx, sc[t]);
        float sum = 0.f;
        #pragma unroll
        for (int t = 0; t < K2; t++) { sc[t] = __expf(sc[t] - mx); sum += sc[t]; }
        float inv = 1.f / sum;
        #pragma unroll
        for (int t = 0; t < K2; t++) sc[t] *= inv;
    }
    __syncthreads();

    // ---- phase 2: V halo fill (same buffer) ----
    for (int idx = tid; idx < HALOSZ * 8; idx += 256) {
        int hp = idx >> 3;
        int c4 = (idx & 7) * 4;
        int gy = ty0 - 3 + hp / HALO;
        int gx = tx0 - 3 + hp % HALO;
        float4 vv = *reinterpret_cast<const float4*>(g_bcv + cbase + c4);
        if (gy >= 0 && gy < 56 && gx >= 0 && gx < 56) {
            float4 v4 = *reinterpret_cast<const float4*>(Vp + (size_t)(gy * 56 + gx) * CH + cbase + c4);
            vv.x += v4.x; vv.y += v4.y; vv.z += v4.z; vv.w += v4.w;
        }
        *reinterpret_cast<float4*>(smf + hp * ROWP + c4) = vv;
    }
    __syncthreads();

    if (active) {
        float4 o4[8];
        #pragma unroll
        for (int c = 0; c < 8; c++) o4[c] = make_float4(0.f, 0.f, 0.f, 0.f);
        #pragma unroll
        for (int ti = 0; ti < KER; ti++) {
            #pragma unroll
            for (int tj = 0; tj < KER; tj++) {
                const float4* vr = reinterpret_cast<const float4*>(
                    smf + ((ly + ti) * HALO + (lx + tj)) * ROWP);
                float wgt = sc[ti * KER + tj];
                #pragma unroll
                for (int c = 0; c < 8; c++) {
                    float4 v4 = vr[c];
                    o4[c].x += wgt * v4.x; o4[c].y += wgt * v4.y;
                    o4[c].z += wgt * v4.z; o4[c].w += wgt * v4.w;
                }
            }
        }
        float* optr = g_O + (size_t)n * PPIX * CH + (size_t)p * CH + cbase;
        #pragma unroll
        for (int i = 0; i < 8; i++)
            *reinterpret_cast<float4*>(optr + i * 4) = o4[i];
    }
}

// ---------------------------------------------------------------------------
// Out projection (tf32, BM=64 BN=64 BK=32, cp.async 3-stage, 128 threads):
//   out[n][c'][p] = sum_c O[n][p][c] * Wout[c'][c] + bout[c']
// O row-major (m,k) -> A smem m-major f32 [64][36].
// ---------------------------------------------------------------------------
__global__ void __launch_bounds__(128, 4)
outproj_gemm(const float* __restrict__ Wout, const float* __restrict__ bout,
             float* __restrict__ out) {
    int nb = blockIdx.z;
    const float* A = g_O + (size_t)nb * PPIX * CH;

    extern __shared__ float smf[];     // [NSTG][STG_F]

    int tid = threadIdx.x;
    int m0 = blockIdx.x * 64;
    int c0 = blockIdx.y * 64;
    int w = tid >> 5, lane = tid & 31;
    int r = lane >> 2, tig = lane & 3;
    int wm = (w & 1) * 32;
    int wn = (w >> 1) * 32;

    float acc[2][4][4] = {};

    auto issue_tile = [&](int t, int stg) {
        float* As = smf + stg * STG_F;
        float* Bs = As + 2304;
        int kt = t * 32;
        #pragma unroll
        for (int i = 0; i < 4; i++) {
            int id = tid + 128 * i;
            int row = id >> 3;                 // 0..63
            int k4 = (id & 7) * 4;
            cp16(As + row * 36 + k4, A + (size_t)(m0 + row) * CH + kt + k4);
        }
        #pragma unroll
        for (int i = 0; i < 4; i++) {
            int id = tid + 128 * i;
            int row = id >> 3;
            int k4 = (id & 7) * 4;
            cp16(Bs + row * 36 + k4, Wout + (size_t)(c0 + row) * CH + kt + k4);
        }
        CP_COMMIT();
    };

    issue_tile(0, 0);
    issue_tile(1, 1);

    for (int it = 0; it < 8; it++) {
        CP_WAIT1();
        __syncthreads();
        if (it + 2 < 8) issue_tile(it + 2, (it + 2) % NSTG);

        const float* Ab = smf + (it % NSTG) * STG_F;
        const float* Bb = Ab + 2304;
        #pragma unroll
        for (int ks = 0; ks < 4; ks++) {
            int k0 = ks * 8;
            uint32_t a[2][4], b[4][2];
            #pragma unroll
            for (int mt = 0; mt < 2; mt++) {
                int m = wm + mt * 16 + r;
                a[mt][0] = f2tf(Ab[m * 36 + k0 + tig]);
                a[mt][1] = f2tf(Ab[(m + 8) * 36 + k0 + tig]);
                a[mt][2] = f2tf(Ab[m * 36 + k0 + tig + 4]);
                a[mt][3] = f2tf(Ab[(m + 8) * 36 + k0 + tig + 4]);
            }
            #pragma unroll
            for (int nt = 0; nt < 4; nt++) {
                int nn = wn + nt * 8 + r;
                b[nt][0] = f2tf(Bb[nn * 36 + k0 + tig]);
                b[nt][1] = f2tf(Bb[nn * 36 + k0 + tig + 4]);
            }
            #pragma unroll
            for (int mt = 0; mt < 2; mt++)
                #pragma unroll
                for (int nt = 0; nt < 4; nt++)
                    mma_tf32(acc[mt][nt], a[mt], b[nt]);
        }
    }

    // epilogue: transposed store out[c'][p]
    float* ob = out + (size_t)nb * CH * PPIX;
    #pragma unroll
    for (int mt = 0; mt < 2; mt++) {
        int row0 = m0 + wm + mt * 16 + r;
        #pragma unroll
        for (int nt = 0; nt < 4; nt++) {
            int cc = c0 + wn + nt * 8 + 2 * tig;
            float b0 = bout[cc], b1 = bout[cc + 1];
            ob[(size_t)cc * PPIX + row0]           = acc[mt][nt][0] + b0;
            ob[(size_t)(cc + 1) * PPIX + row0]     = acc[mt][nt][1] + b1;
            ob[(size_t)cc * PPIX + row0 + 8]       = acc[mt][nt][2] + b0;
            ob[(size_t)(cc + 1) * PPIX + row0 + 8] = acc[mt][nt][3] + b1;
        }
    }
}

extern "C" void kernel_launch(void* const* d_in, const int* in_sizes, int n_in,
                              void* d_out, int out_size) {
    const float* queries = (const float*)d_in[0];
    const float* key     = (const float*)d_in[1];
    const float* pos     = (const float*)d_in[2];
    const float* ipw     = (const float*)d_in[3];
    const float* ipb     = (const float*)d_in[4];
    const float* opw     = (const float*)d_in[5];
    const float* opb     = (const float*)d_in[6];
    float* out = (float*)d_out;

    const int gemm_smem = NSTG * STG_F * (int)sizeof(float);    // 55296
    const int attn_smem = HALOSZ * ROWP * (int)sizeof(float);   // 57600

    cudaFuncSetAttribute(proj_gemm,    cudaFuncAttributeMaxDynamicSharedMemorySize, gemm_smem);
    cudaFuncSetAttribute(outproj_gemm, cudaFuncAttributeMaxDynamicSharedMemorySize, gemm_smem);
    cudaFuncSetAttribute(attn_kernel,  cudaFuncAttributeMaxDynamicSharedMemorySize, attn_smem);

    bconst_kernel<<<32, 256>>>(ipw, ipb, pos);
    proj_gemm<<<dim3(49, 4, 6), 128, gemm_smem>>>(queries, key, ipw, ipb);
    attn_kernel<<<dim3(4, 4, 16), 256, attn_smem>>>();
    outproj_gemm<<<dim3(49, 4, 2), 128, gemm_smem>>>(opw, opb, out);
}